// round 12
// baseline (speedup 1.0000x reference)
#include <cuda_runtime.h>
#include <cuda_bf16.h>
#include <cstdint>

#define LSEQ 252
#define HID 768
#define MLP 770
#define NLAB 36
#define BATCH 2
#define KP 784            // MLP padded to 49*16
#define NPH1 1540         // 2*MLP
#define MROWS 504         // BATCH*LSEQ
#define LL (LSEQ*LSEQ)    // 63504
#define LL4 (LL/4)        // 15876
#define W1STRIDE 1537     // 2*HID+1
#define NPART 16          // softmax partial-sum slots per (b,k)
#define NIT_PER 7         // it-values per persistent block (63 = 9*7)
#define NCHUNK 49         // 784/16 k-chunks
#define KSPLIT 25         // kh=0 does [0,25), kh=1 does [25,49)

// ---- scratch (device globals; no dynamic allocation allowed) ----
__device__ float g_W1r[NPH1 * HID];          // repacked W1 (col-major B operand rows)
__device__ float g_Ai[MROWS * KP];           // Ai, zero-padded cols [770,784)
__device__ float g_Aj[MROWS * KP];
__device__ float g_Cc[3 * KP];               // b1 + c*w1c, c=0..2
__device__ __nv_bfloat16 g_W2b[40 * KP];     // W2 padded 40x784, bf16, k16-pair-permuted
__device__ unsigned g_maxbits[BATCH * NLAB]; // per-(b,k) max (>=0, as float bits)
__device__ float g_psum[BATCH * NLAB * NPART]; // partial exp-sums

// ---------------------------------------------------------------------------
// tf32 mma m16n8k8 (row.col), fp32 accum (phase-1 GEMM)
__device__ __forceinline__ void mma_tf32(float* d, float a0, float a1, float a2, float a3,
                                         float b0, float b1) {
    asm volatile(
        "mma.sync.aligned.m16n8k8.row.col.f32.tf32.tf32.f32 "
        "{%0,%1,%2,%3},{%4,%5,%6,%7},{%8,%9},{%0,%1,%2,%3};\n"
        : "+f"(d[0]), "+f"(d[1]), "+f"(d[2]), "+f"(d[3])
        : "r"(__float_as_uint(a0)), "r"(__float_as_uint(a1)),
          "r"(__float_as_uint(a2)), "r"(__float_as_uint(a3)),
          "r"(__float_as_uint(b0)), "r"(__float_as_uint(b1)));
}

// bf16 mma m16n8k16 (row.col), fp32 accum (main GEMM)
__device__ __forceinline__ void mma_bf16(float* d, unsigned a0, unsigned a1, unsigned a2,
                                         unsigned a3, unsigned b0, unsigned b1) {
    asm volatile(
        "mma.sync.aligned.m16n8k16.row.col.f32.bf16.bf16.f32 "
        "{%0,%1,%2,%3},{%4,%5,%6,%7},{%8,%9},{%0,%1,%2,%3};\n"
        : "+f"(d[0]), "+f"(d[1]), "+f"(d[2]), "+f"(d[3])
        : "r"(a0), "r"(a1), "r"(a2), "r"(a3), "r"(b0), "r"(b1));
}

// pack two floats -> bf16x2 {lo=lo, hi=hi}
__device__ __forceinline__ unsigned pack_bf16(float lo, float hi) {
    unsigned r;
    asm("cvt.rn.bf16x2.f32 %0, %1, %2;" : "=r"(r) : "f"(hi), "f"(lo));
    return r;
}

// ---------------------------------------------------------------------------
// Prep: repack W1, build C vectors, bf16 W2 (k16-permuted), zero pads, reset max.
// k16 permutation within each 16-col chunk: [0,1,8,9, 2,3,10,11, 4,5,12,13, 6,7,14,15]
__global__ void k_prep(const float* __restrict__ W1, const float* __restrict__ b1,
                       const float* __restrict__ W2) {
    int idx = blockIdx.x * blockDim.x + threadIdx.x;
    int stride = gridDim.x * blockDim.x;
    for (int t = idx; t < NPH1 * HID; t += stride) {
        int n = t / HID, k = t - n * HID;
        g_W1r[t] = (n < MLP) ? W1[n * W1STRIDE + k] : W1[(n - MLP) * W1STRIDE + HID + k];
    }
    for (int t = idx; t < 3 * KP; t += stride) {
        int c = t / KP, h = t - c * KP;
        g_Cc[t] = (h < MLP) ? (b1[h] + (float)c * W1[h * W1STRIDE + 2 * HID]) : 0.0f;
    }
    for (int t = idx; t < 40 * KP; t += stride) {
        int n = t / KP, k = t - n * KP;
        float v = (n < NLAB && k < MLP) ? W2[n * MLP + k] : 0.0f;
        int ch = k >> 4, wv = k & 15;
        int pos = (wv < 8) ? ((wv >> 1) * 4 + (wv & 1)) : (((wv & 7) >> 1) * 4 + 2 + (wv & 1));
        g_W2b[n * KP + ch * 16 + pos] = __float2bfloat16(v);
    }
    for (int t = idx; t < MROWS * (KP - MLP); t += stride) {
        int m = t / (KP - MLP), c = MLP + (t - m * (KP - MLP));
        g_Ai[m * KP + c] = 0.0f;
        g_Aj[m * KP + c] = 0.0f;
    }
    for (int t = idx; t < BATCH * NLAB; t += stride) g_maxbits[t] = 0u;
}

// ---------------------------------------------------------------------------
// Phase 1: [504x768] @ [768x1540] tf32 GEMM -> g_Ai / g_Aj (fp32).
__global__ __launch_bounds__(128) void k_ph1(const float* __restrict__ hidden) {
    __shared__ float As[64 * 36];
    __shared__ float Bs[64 * 36];
    const int tid = threadIdx.x, lane = tid & 31, w = tid >> 5;
    const int m0 = blockIdx.y * 64, n0 = blockIdx.x * 64;
    const int wm = w >> 1, wn = w & 1;
    const int r = lane >> 2, kq = lane & 3;

    float acc[2][4][4];
#pragma unroll
    for (int a = 0; a < 2; a++)
#pragma unroll
        for (int b = 0; b < 4; b++)
#pragma unroll
            for (int c = 0; c < 4; c++) acc[a][b][c] = 0.0f;

    for (int kc = 0; kc < 24; kc++) {
        const int k0 = kc * 32;
#pragma unroll
        for (int p = 0; p < 4; p++) {
            int i = tid + p * 128;
            int row = i >> 3, c8 = i & 7;
            int m = m0 + row;
            float4 v = make_float4(0.f, 0.f, 0.f, 0.f);
            if (m < MROWS) {
                int b = m / LSEQ, l = m - b * LSEQ;
                v = *(const float4*)&hidden[((size_t)(b * (LSEQ + 1) + l + 1)) * HID + k0 + c8 * 4];
            }
            *(float4*)&As[row * 36 + c8 * 4] = v;
        }
#pragma unroll
        for (int p = 0; p < 4; p++) {
            int i = tid + p * 128;
            int row = i >> 3, c8 = i & 7;
            int n = n0 + row;
            float4 v = make_float4(0.f, 0.f, 0.f, 0.f);
            if (n < NPH1) v = *(const float4*)&g_W1r[(size_t)n * HID + k0 + c8 * 4];
            *(float4*)&Bs[row * 36 + c8 * 4] = v;
        }
        __syncthreads();
#pragma unroll
        for (int kk = 0; kk < 4; kk++) {
            const int kb = kk * 8 + kq;
            float a[2][4];
#pragma unroll
            for (int mf = 0; mf < 2; mf++) {
                int rb = wm * 32 + mf * 16 + r;
                a[mf][0] = As[rb * 36 + kb];
                a[mf][1] = As[(rb + 8) * 36 + kb];
                a[mf][2] = As[rb * 36 + kb + 4];
                a[mf][3] = As[(rb + 8) * 36 + kb + 4];
            }
#pragma unroll
            for (int nf = 0; nf < 4; nf++) {
                int nr = wn * 32 + nf * 8 + r;
                float b0 = Bs[nr * 36 + kb];
                float b1 = Bs[nr * 36 + kb + 4];
                mma_tf32(acc[0][nf], a[0][0], a[0][1], a[0][2], a[0][3], b0, b1);
                mma_tf32(acc[1][nf], a[1][0], a[1][1], a[1][2], a[1][3], b0, b1);
            }
        }
        __syncthreads();
    }
#pragma unroll
    for (int mf = 0; mf < 2; mf++) {
#pragma unroll
        for (int nf = 0; nf < 4; nf++) {
            int mg = m0 + wm * 32 + mf * 16 + r;
            int ng = n0 + wn * 32 + nf * 8 + kq * 2;
            if (ng < NPH1) {
                float* dst = (ng < MLP) ? &g_Ai[0] : &g_Aj[0];
                int col = (ng < MLP) ? ng : ng - MLP;
                if (mg < MROWS) {
                    float2 v = make_float2(acc[mf][nf][0], acc[mf][nf][1]);
                    *(float2*)&dst[(size_t)mg * KP + col] = v;
                }
                if (mg + 8 < MROWS) {
                    float2 v = make_float2(acc[mf][nf][2], acc[mf][nf][3]);
                    *(float2*)&dst[(size_t)(mg + 8) * KP + col] = v;
                }
            }
        }
    }
}

// ---------------------------------------------------------------------------
// Main fused kernel: 512 threads (16 warps), persistent over NIT_PER i-tiles,
// bf16 m16n8k16 MMA, warp pairs split the 49 k-chunks, smem-scratch reduction.
#define AJ_STRIDE 808   // floats; ==8 mod 32 -> conflict-free LDS.64 phases
#define SMEM_MAIN ((32 * AJ_STRIDE + 12 * AJ_STRIDE) * 4 + 40 * KP * 2 + 128 + 8 * 32 * 20 * 4)

__global__ __launch_bounds__(512, 1) void k_main(const int* __restrict__ spans,
                                                 const int* __restrict__ smask,
                                                 const float* __restrict__ b2,
                                                 float* __restrict__ out) {
    extern __shared__ char smem[];
    float* AjS = (float*)smem;                                   // [32][808] fp32, natural
    float* AiC = AjS + 32 * AJ_STRIDE;                           // [4][3][808]
    __nv_bfloat16* W2s = (__nv_bfloat16*)(AiC + 12 * AJ_STRIDE); // [40][784] k16-permuted
    unsigned char* cf = (unsigned char*)((char*)W2s + 40 * KP * 2); // [4][32]
    float* scr = (float*)(cf + 128);                             // [8][32][20] partial accs

    const int tid = threadIdx.x;
    const int b = blockIdx.z, itc = blockIdx.y, jt = blockIdx.x;
    const int j0 = jt * 32;
    const int s = spans[b * 2], e = spans[b * 2 + 1];

    // ---- one-time prologue: Aj tile (natural fp32) + W2 tile (straight copy) ----
    for (int u = tid; u < 32 * 196; u += 512) {
        int row = u / 196, c4 = u - row * 196;
        int j = j0 + row;
        float4 v = make_float4(0.f, 0.f, 0.f, 0.f);
        if (j < LSEQ) v = *(const float4*)&g_Aj[(size_t)(b * LSEQ + j) * KP + c4 * 4];
        *(float4*)&AjS[row * AJ_STRIDE + c4 * 4] = v;
    }
    for (int u = tid; u < 40 * 98; u += 512)
        ((uint4*)W2s)[u] = ((const uint4*)g_W2b)[u];

    const int lane = tid & 31, w = tid >> 5;
    const int il = w >> 2, jh = (w >> 1) & 1, kh = w & 1;
    const int j0l = jh * 16;
    const int r = lane >> 2, kq = lane & 3;
    const int jr0 = j0l + r, jr1 = jr0 + 8;
    const int jg0 = j0 + jr0, jg1 = j0 + jr1;
    const int ks_begin = kh ? KSPLIT : 0;
    const int ks_end = kh ? NCHUNK : KSPLIT;
    float* myscr = scr + ((w >> 1) * 32 + lane) * 20;

    // per-thread biases
    float bb[5][2];
#pragma unroll
    for (int nt = 0; nt < 5; nt++) {
        int k0 = nt * 8 + kq * 2;
        bb[nt][0] = (k0 < NLAB) ? b2[k0] : 0.0f;
        bb[nt][1] = (k0 + 1 < NLAB) ? b2[k0 + 1] : 0.0f;
    }
    // running per-k max (masked entries are 0 -> init 0); kh=0 warps only use it
    float mx[5][2];
#pragma unroll
    for (int nt = 0; nt < 5; nt++) mx[nt][0] = mx[nt][1] = 0.0f;

    for (int t7 = 0; t7 < NIT_PER; t7++) {
        const int it = itc * NIT_PER + t7;
        const int i0 = it * 4;

        __syncthreads();  // prev epilogue done before AiC/cf overwrite
        // AiC = Ai[i0+ill] + Cc[c] (natural layout)
        for (int u = tid; u < 12 * 196; u += 512) {
            int rc = u / 196, c4 = u - rc * 196;
            int ill = rc / 3, c = rc - ill * 3;
            float4 a = *(const float4*)&g_Ai[(size_t)(b * LSEQ + i0 + ill) * KP + c4 * 4];
            float4 cc = *(const float4*)&g_Cc[c * KP + c4 * 4];
            *(float4*)&AiC[rc * AJ_STRIDE + c4 * 4] =
                make_float4(a.x + cc.x, a.y + cc.y, a.z + cc.z, a.w + cc.w);
        }
        for (int t = tid; t < 4 * 32; t += 512) {
            int ill = t >> 5, jl = t & 31;
            int i = i0 + ill, j = j0 + jl;
            int c = 0, valid = 0;
            if (j < LSEQ) {
                valid = (smask[i * LSEQ + j] >= 1) ? 1 : 0;
                if (s <= i && i <= j && j <= e) c = (i == s && j == e) ? 2 : 1;
            }
            cf[t] = (unsigned char)(c | (valid << 2));
        }
        __syncthreads();

        const int f0 = cf[il * 32 + jr0], f1 = cf[il * 32 + jr1];
        const float* aj0 = AjS + jr0 * AJ_STRIDE + 2 * kq;
        const float* aj1 = AjS + jr1 * AJ_STRIDE + 2 * kq;
        const float* ac0 = AiC + (il * 3 + (f0 & 3)) * AJ_STRIDE + 2 * kq;
        const float* ac1 = AiC + (il * 3 + (f1 & 3)) * AJ_STRIDE + 2 * kq;
        const __nv_bfloat16* wp = W2s + r * KP + kq * 4;

        float acc[5][4];
#pragma unroll
        for (int nt = 0; nt < 5; nt++)
#pragma unroll
            for (int q = 0; q < 4; q++) acc[nt][q] = 0.0f;

#pragma unroll 2
        for (int ks = ks_begin; ks < ks_end; ks++) {
            const int off = ks * 16;
            float2 j0lo = *(const float2*)(aj0 + off);
            float2 c0lo = *(const float2*)(ac0 + off);
            float2 j1lo = *(const float2*)(aj1 + off);
            float2 c1lo = *(const float2*)(ac1 + off);
            float2 j0hi = *(const float2*)(aj0 + off + 8);
            float2 c0hi = *(const float2*)(ac0 + off + 8);
            float2 j1hi = *(const float2*)(aj1 + off + 8);
            float2 c1hi = *(const float2*)(ac1 + off + 8);
            unsigned a0 = pack_bf16(fmaxf(j0lo.x + c0lo.x, 0.f), fmaxf(j0lo.y + c0lo.y, 0.f));
            unsigned a1 = pack_bf16(fmaxf(j1lo.x + c1lo.x, 0.f), fmaxf(j1lo.y + c1lo.y, 0.f));
            unsigned a2 = pack_bf16(fmaxf(j0hi.x + c0hi.x, 0.f), fmaxf(j0hi.y + c0hi.y, 0.f));
            unsigned a3 = pack_bf16(fmaxf(j1hi.x + c1hi.x, 0.f), fmaxf(j1hi.y + c1hi.y, 0.f));
#pragma unroll
            for (int nt = 0; nt < 5; nt++) {
                uint2 bv = *(const uint2*)(wp + (size_t)nt * 8 * KP + off);
                mma_bf16(acc[nt], a0, a1, a2, a3, bv.x, bv.y);
            }
        }

        // reduce kh=1 partials into kh=0 via smem scratch
        if (kh == 1) {
#pragma unroll
            for (int nt = 0; nt < 5; nt++)
                *(float4*)(myscr + nt * 4) =
                    make_float4(acc[nt][0], acc[nt][1], acc[nt][2], acc[nt][3]);
        }
        __syncthreads();
        if (kh == 0) {
#pragma unroll
            for (int nt = 0; nt < 5; nt++) {
                float4 v = *(const float4*)(myscr + nt * 4);
                acc[nt][0] += v.x;
                acc[nt][1] += v.y;
                acc[nt][2] += v.z;
                acc[nt][3] += v.w;
            }
            // epilogue: +b2, mask, store; track per-k max
            const int i = i0 + il;
            const int v0 = (f0 >> 2) & 1, v1 = (f1 >> 2) & 1;
#pragma unroll
            for (int nt = 0; nt < 5; nt++) {
                int k0 = nt * 8 + kq * 2;
                if (k0 < NLAB) {
                    if (jg0 < LSEQ) {
                        float s0 = v0 ? (acc[nt][0] + bb[nt][0]) : 0.0f;
                        float s1 = v0 ? (acc[nt][1] + bb[nt][1]) : 0.0f;
                        size_t p0 = (size_t)(b * NLAB + k0) * LL + i * LSEQ + jg0;
                        out[p0] = s0;
                        out[p0 + LL] = s1;
                        mx[nt][0] = fmaxf(mx[nt][0], s0);
                        mx[nt][1] = fmaxf(mx[nt][1], s1);
                    }
                    if (jg1 < LSEQ) {
                        float s0 = v1 ? (acc[nt][2] + bb[nt][0]) : 0.0f;
                        float s1 = v1 ? (acc[nt][3] + bb[nt][1]) : 0.0f;
                        size_t p1 = (size_t)(b * NLAB + k0) * LL + i * LSEQ + jg1;
                        out[p1] = s0;
                        out[p1 + LL] = s1;
                        mx[nt][0] = fmaxf(mx[nt][0], s0);
                        mx[nt][1] = fmaxf(mx[nt][1], s1);
                    }
                }
            }
        }
    }

    // fold max over r-lanes, then atomicMax (kh=0 warps only)
    if (kh == 0) {
#pragma unroll
        for (int nt = 0; nt < 5; nt++) {
#pragma unroll
            for (int q = 0; q < 2; q++) {
                float m = mx[nt][q];
                m = fmaxf(m, __shfl_xor_sync(0xFFFFFFFFu, m, 4));
                m = fmaxf(m, __shfl_xor_sync(0xFFFFFFFFu, m, 8));
                m = fmaxf(m, __shfl_xor_sync(0xFFFFFFFFu, m, 16));
                int k0 = nt * 8 + kq * 2 + q;
                if (r == 0 && k0 < NLAB)
                    atomicMax(&g_maxbits[b * NLAB + k0], __float_as_uint(m));
            }
        }
    }
}

// ---------------------------------------------------------------------------
// Partial sum of exp(x - M); 4 independent accumulator chains + 2-way load ILP.
__global__ __launch_bounds__(256) void k_sumexp(const float* __restrict__ out) {
    const int bk = blockIdx.y;
    const float4* p = (const float4*)(out + (size_t)bk * LL);
    const float M = __uint_as_float(g_maxbits[bk]);
    const float L2E = 1.4426950408889634f;
    const float nML2E = -M * L2E;
    const int STR = NPART * 256;
    float s0 = 0.f, s1 = 0.f, s2 = 0.f, s3 = 0.f;
    for (int t = blockIdx.x * 256 + threadIdx.x; t < LL4; t += 2 * STR) {
        float4 v = p[t];
        float4 u = make_float4(0.f, 0.f, 0.f, 0.f);
        int t2 = t + STR;
        bool hi = (t2 < LL4);
        if (hi) u = p[t2];
        s0 += exp2f(fmaf(v.x, L2E, nML2E));
        s1 += exp2f(fmaf(v.y, L2E, nML2E));
        s2 += exp2f(fmaf(v.z, L2E, nML2E));
        s3 += exp2f(fmaf(v.w, L2E, nML2E));
        if (hi) {
            s0 += exp2f(fmaf(u.x, L2E, nML2E));
            s1 += exp2f(fmaf(u.y, L2E, nML2E));
            s2 += exp2f(fmaf(u.z, L2E, nML2E));
            s3 += exp2f(fmaf(u.w, L2E, nML2E));
        }
    }
    float s = (s0 + s1) + (s2 + s3);
#pragma unroll
    for (int o = 16; o > 0; o >>= 1) s += __shfl_xor_sync(0xFFFFFFFFu, s, o);
    __shared__ float sm[8];
    if ((threadIdx.x & 31) == 0) sm[threadIdx.x >> 5] = s;
    __syncthreads();
    if (threadIdx.x == 0) {
        float ss = 0.f;
#pragma unroll
        for (int q = 0; q < 8; q++) ss += sm[q];
        g_psum[bk * NPART + blockIdx.x] = ss;  // fixed slot -> deterministic
    }
}

// Combine partials (fixed order) + subtract lse.
__global__ __launch_bounds__(256) void k_sub(float* __restrict__ out) {
    const int bk = blockIdx.y;
    __shared__ float lse_s;
    if (threadIdx.x == 0) {
        float M = __uint_as_float(g_maxbits[bk]);
        float s = 0.f;
#pragma unroll
        for (int q = 0; q < NPART; q++) s += g_psum[bk * NPART + q];
        lse_s = M + logf(s);
    }
    __syncthreads();
    const float lse = lse_s;
    int t = blockIdx.x * 256 + threadIdx.x;
    if (t < LL4) {
        float4* p = (float4*)(out + (size_t)bk * LL);
        float4 v = p[t];
        v.x -= lse;
        v.y -= lse;
        v.z -= lse;
        v.w -= lse;
        p[t] = v;
    }
}

// ---------------------------------------------------------------------------
extern "C" void kernel_launch(void* const* d_in, const int* in_sizes, int n_in,
                              void* d_out, int out_size) {
    const float* hidden = (const float*)d_in[0];
    const int* spans = (const int*)d_in[1];
    const int* smask = (const int*)d_in[2];
    const float* W1 = (const float*)d_in[3];
    const float* b1 = (const float*)d_in[4];
    const float* W2 = (const float*)d_in[5];
    const float* b2 = (const float*)d_in[6];
    float* out = (float*)d_out;

    cudaFuncSetAttribute(k_main, cudaFuncAttributeMaxDynamicSharedMemorySize, SMEM_MAIN);

    k_prep<<<256, 256>>>(W1, b1, W2);
    k_ph1<<<dim3(25, 8), 128>>>(hidden);
    k_main<<<dim3(8, 9, 2), 512, SMEM_MAIN>>>(spans, smask, b2, out);
    k_sumexp<<<dim3(NPART, BATCH * NLAB), 256>>>(out);
    k_sub<<<dim3((LL4 + 255) / 256, BATCH * NLAB), 256>>>(out);
}

// round 14
// speedup vs baseline: 1.4150x; 1.4150x over previous
#include <cuda_runtime.h>
#include <cuda_bf16.h>
#include <cstdint>

#define LSEQ 252
#define HID 768
#define MLP 770
#define NLAB 36
#define BATCH 2
#define KP 784            // MLP padded to 49*16
#define KP2 392           // KP/2 (bf16x2 pairs)
#define NPH1 1540         // 2*MLP
#define MROWS 504         // BATCH*LSEQ
#define LL (LSEQ*LSEQ)    // 63504
#define LL4 (LL/4)        // 15876
#define W1STRIDE 1537     // 2*HID+1
#define NPART 16          // softmax partial-sum slots per (b,k)
#define NIT_PER 7         // i-slabs per persistent block (63 = 9*7)
#define NCHUNK 49         // k16 chunks
#define JT 16             // j's per block
#define AJW 392           // words (bf16x2 pairs) per row; 392 mod 32 = 8

// ---- scratch (device globals; no dynamic allocation allowed) ----
__device__ float g_W1r[NPH1 * HID];            // repacked W1 (B operand rows)
__device__ float g_Ai[MROWS * KP];             // Ai fp32, zero-padded cols [770,784)
__device__ uint32_t g_Ajh[MROWS * KP2];        // Aj bf16x2, PAIR-PERMUTED, pads zeroed
__device__ float g_Cc[3 * KP];                 // b1 + c*w1c, c=0..2
__device__ uint32_t g_W2b[40 * KP2];           // W2 40x784 bf16, k16-element-permuted
__device__ unsigned g_maxbits[BATCH * NLAB];   // per-(b,k) max (>=0, float bits)
__device__ float g_psum[BATCH * NLAB * NPART]; // partial exp-sums

// ---------------------------------------------------------------------------
// pair permutation within each 8-pair (16-element) group:
// stored order [p0,p4,p1,p5,p2,p6,p3,p7] -> LDS.64 at 2*kq gives (p_kq, p_{kq+4})
__device__ __forceinline__ int permp(int p) {
    int g = p >> 3, q = p & 7;
    return g * 8 + ((q & 3) << 1) + (q >> 2);
}

__device__ __forceinline__ unsigned pack_bf16(float lo, float hi) {
    unsigned r;
    asm("cvt.rn.bf16x2.f32 %0, %1, %2;" : "=r"(r) : "f"(hi), "f"(lo));
    return r;
}
__device__ __forceinline__ __nv_bfloat162 u2b(uint32_t x) {
    return *(__nv_bfloat162*)&x;
}
__device__ __forceinline__ uint32_t b2u(__nv_bfloat162 x) {
    return *(uint32_t*)&x;
}

// tf32 mma m16n8k8 (phase-1 GEMM)
__device__ __forceinline__ void mma_tf32(float* d, float a0, float a1, float a2, float a3,
                                         float b0, float b1) {
    asm volatile(
        "mma.sync.aligned.m16n8k8.row.col.f32.tf32.tf32.f32 "
        "{%0,%1,%2,%3},{%4,%5,%6,%7},{%8,%9},{%0,%1,%2,%3};\n"
        : "+f"(d[0]), "+f"(d[1]), "+f"(d[2]), "+f"(d[3])
        : "r"(__float_as_uint(a0)), "r"(__float_as_uint(a1)),
          "r"(__float_as_uint(a2)), "r"(__float_as_uint(a3)),
          "r"(__float_as_uint(b0)), "r"(__float_as_uint(b1)));
}
// bf16 mma m16n8k16 (main GEMM)
__device__ __forceinline__ void mma_bf16(float* d, unsigned a0, unsigned a1, unsigned a2,
                                         unsigned a3, unsigned b0, unsigned b1) {
    asm volatile(
        "mma.sync.aligned.m16n8k16.row.col.f32.bf16.bf16.f32 "
        "{%0,%1,%2,%3},{%4,%5,%6,%7},{%8,%9},{%0,%1,%2,%3};\n"
        : "+f"(d[0]), "+f"(d[1]), "+f"(d[2]), "+f"(d[3])
        : "r"(a0), "r"(a1), "r"(a2), "r"(a3), "r"(b0), "r"(b1));
}

// ---------------------------------------------------------------------------
// Prep: repack W1, C vectors, W2 (k16 element perm), pads, reset max.
// W2 element perm within 16-chunk: [0,1,8,9, 2,3,10,11, 4,5,12,13, 6,7,14,15]
// (identical to the validated round-12 layout)
__global__ void k_prep(const float* __restrict__ W1, const float* __restrict__ b1,
                       const float* __restrict__ W2) {
    int idx = blockIdx.x * blockDim.x + threadIdx.x;
    int stride = gridDim.x * blockDim.x;
    for (int t = idx; t < NPH1 * HID; t += stride) {
        int n = t / HID, k = t - n * HID;
        g_W1r[t] = (n < MLP) ? W1[n * W1STRIDE + k] : W1[(n - MLP) * W1STRIDE + HID + k];
    }
    for (int t = idx; t < 3 * KP; t += stride) {
        int c = t / KP, h = t - c * KP;
        g_Cc[t] = (h < MLP) ? (b1[h] + (float)c * W1[h * W1STRIDE + 2 * HID]) : 0.0f;
    }
    for (int t = idx; t < 40 * KP2; t += stride) {  // build as bf16x2 words
        int n = t / KP2, p = t - n * KP2;           // p = stored pair index
        // invert: stored pair p holds elements (2m, 2m+1) of logical perm... easier:
        // stored halves at positions 2p,2p+1. pos -> logical k: within chunk,
        // pos = (kk>>1)*4 + (kk&1) for kk<8 ; = ((kk&7)>>1)*4+2+(kk&1) for kk>=8.
        // invert per position pos (0..15): q = pos>>2 (which kq group), rph = pos&3:
        //   rph 0,1 -> kk = 2q + (pos&1); rph 2,3 -> kk = 8 + 2q + (pos&1)
        int ch = p >> 3, pin = p & 7;               // pair within chunk (0..7)
        int pos0 = pin * 2, pos1 = pin * 2 + 1;
        int q0 = pos0 >> 2, q1 = pos1 >> 2;
        int k0 = ch * 16 + (((pos0 & 3) < 2) ? (2 * q0 + (pos0 & 1)) : (8 + 2 * q0 + (pos0 & 1)));
        int k1 = ch * 16 + (((pos1 & 3) < 2) ? (2 * q1 + (pos1 & 1)) : (8 + 2 * q1 + (pos1 & 1)));
        float v0 = (n < NLAB && k0 < MLP) ? W2[n * MLP + k0] : 0.0f;
        float v1 = (n < NLAB && k1 < MLP) ? W2[n * MLP + k1] : 0.0f;
        g_W2b[t] = pack_bf16(v0, v1);
    }
    for (int t = idx; t < MROWS * (KP - MLP); t += stride) {
        int m = t / (KP - MLP), c = MLP + (t - m * (KP - MLP));
        g_Ai[m * KP + c] = 0.0f;
    }
    for (int t = idx; t < MROWS * 7; t += stride) {  // Aj pad pairs 385..391 (perm-closed set)
        int m = t / 7, p = 385 + (t - m * 7);
        g_Ajh[m * KP2 + p] = 0u;
    }
    for (int t = idx; t < BATCH * NLAB; t += stride) g_maxbits[t] = 0u;
}

// ---------------------------------------------------------------------------
// Phase 1: [504x768] @ [768x1540] tf32 GEMM -> g_Ai (fp32) / g_Ajh (bf16x2, permuted).
__global__ __launch_bounds__(128) void k_ph1(const float* __restrict__ hidden) {
    __shared__ float As[64 * 36];
    __shared__ float Bs[64 * 36];
    const int tid = threadIdx.x, lane = tid & 31, w = tid >> 5;
    const int m0 = blockIdx.y * 64, n0 = blockIdx.x * 64;
    const int wm = w >> 1, wn = w & 1;
    const int r = lane >> 2, kq = lane & 3;

    float acc[2][4][4];
#pragma unroll
    for (int a = 0; a < 2; a++)
#pragma unroll
        for (int b = 0; b < 4; b++)
#pragma unroll
            for (int c = 0; c < 4; c++) acc[a][b][c] = 0.0f;

    for (int kc = 0; kc < 24; kc++) {
        const int k0 = kc * 32;
#pragma unroll
        for (int p = 0; p < 4; p++) {
            int i = tid + p * 128;
            int row = i >> 3, c8 = i & 7;
            int m = m0 + row;
            float4 v = make_float4(0.f, 0.f, 0.f, 0.f);
            if (m < MROWS) {
                int b = m / LSEQ, l = m - b * LSEQ;
                v = *(const float4*)&hidden[((size_t)(b * (LSEQ + 1) + l + 1)) * HID + k0 + c8 * 4];
            }
            *(float4*)&As[row * 36 + c8 * 4] = v;
        }
#pragma unroll
        for (int p = 0; p < 4; p++) {
            int i = tid + p * 128;
            int row = i >> 3, c8 = i & 7;
            int n = n0 + row;
            float4 v = make_float4(0.f, 0.f, 0.f, 0.f);
            if (n < NPH1) v = *(const float4*)&g_W1r[(size_t)n * HID + k0 + c8 * 4];
            *(float4*)&Bs[row * 36 + c8 * 4] = v;
        }
        __syncthreads();
#pragma unroll
        for (int kk = 0; kk < 4; kk++) {
            const int kb = kk * 8 + kq;
            float a[2][4];
#pragma unroll
            for (int mf = 0; mf < 2; mf++) {
                int rb = wm * 32 + mf * 16 + r;
                a[mf][0] = As[rb * 36 + kb];
                a[mf][1] = As[(rb + 8) * 36 + kb];
                a[mf][2] = As[rb * 36 + kb + 4];
                a[mf][3] = As[(rb + 8) * 36 + kb + 4];
            }
#pragma unroll
            for (int nf = 0; nf < 4; nf++) {
                int nr = wn * 32 + nf * 8 + r;
                float b0 = Bs[nr * 36 + kb];
                float b1 = Bs[nr * 36 + kb + 4];
                mma_tf32(acc[0][nf], a[0][0], a[0][1], a[0][2], a[0][3], b0, b1);
                mma_tf32(acc[1][nf], a[1][0], a[1][1], a[1][2], a[1][3], b0, b1);
            }
        }
        __syncthreads();
    }
#pragma unroll
    for (int mf = 0; mf < 2; mf++) {
#pragma unroll
        for (int nf = 0; nf < 4; nf++) {
            int mg = m0 + wm * 32 + mf * 16 + r;
            int ng = n0 + wn * 32 + nf * 8 + kq * 2;
            if (ng < NPH1) {
                if (ng < MLP) {
                    if (mg < MROWS)
                        *(float2*)&g_Ai[(size_t)mg * KP + ng] =
                            make_float2(acc[mf][nf][0], acc[mf][nf][1]);
                    if (mg + 8 < MROWS)
                        *(float2*)&g_Ai[(size_t)(mg + 8) * KP + ng] =
                            make_float2(acc[mf][nf][2], acc[mf][nf][3]);
                } else {
                    int p = permp((ng - MLP) >> 1);
                    if (mg < MROWS)
                        g_Ajh[(size_t)mg * KP2 + p] = pack_bf16(acc[mf][nf][0], acc[mf][nf][1]);
                    if (mg + 8 < MROWS)
                        g_Ajh[(size_t)(mg + 8) * KP2 + p] =
                            pack_bf16(acc[mf][nf][2], acc[mf][nf][3]);
                }
            }
        }
    }
}

// ---------------------------------------------------------------------------
// Main fused kernel: 16-j blocks, 256 threads, OCCUPANCY 2, persistent over 7
// i-slabs. 8 warps = 4 i-rows x 2 n-halves (nt 0-2 / nt 3-4) -> no reduction.
// All operands bf16x2, pair-permuted -> every fragment is one LDS.64.
#define SMW_AJ 0                      // [16][392] uint32
#define SMW_AIC (16 * AJW)            // [12][392]
#define SMW_W2 (28 * AJW)             // [40][392]
#define SMW_B2 (68 * AJW)             // 40 floats
#define SMW_CF (68 * AJW + 40)        // 64 bytes (16 words)
#define SMEM_MAIN ((68 * AJW + 40 + 16) * 4)

__global__ __launch_bounds__(256, 2) void k_main(const int* __restrict__ spans,
                                                 const int* __restrict__ smask,
                                                 const float* __restrict__ b2,
                                                 float* __restrict__ out) {
    extern __shared__ uint32_t smw[];
    uint32_t* AjS = smw + SMW_AJ;
    uint32_t* AiC = smw + SMW_AIC;
    uint32_t* W2s = smw + SMW_W2;
    float* b2s = (float*)(smw + SMW_B2);
    unsigned char* cf = (unsigned char*)(smw + SMW_CF);

    const int tid = threadIdx.x;
    const int b = blockIdx.z, itc = blockIdx.y, jt = blockIdx.x;
    const int j0 = jt * JT;
    const int s = spans[b * 2], e = spans[b * 2 + 1];

    // ---- one-time prologue ----
    for (int u = tid; u < JT * AJW; u += 256) {
        int row = u / AJW, p = u - row * AJW;
        int j = j0 + row;
        AjS[u] = (j < LSEQ) ? g_Ajh[(size_t)(b * LSEQ + j) * KP2 + p] : 0u;
    }
    for (int u = tid; u < 40 * AJW / 4; u += 256)
        ((uint4*)W2s)[u] = ((const uint4*)g_W2b)[u];
    if (tid < 40) b2s[tid] = (tid < NLAB) ? b2[tid] : 0.0f;

    const int lane = tid & 31, w = tid >> 5;
    const int il = w >> 1, nh = w & 1;
    const int ntb = nh * 3, ntn = 3 - nh;  // nh0: nt 0,1,2 ; nh1: nt 3,4
    const int r = lane >> 2, kq = lane & 3;
    const int jr0 = r, jr1 = r + 8;
    const int jg0 = j0 + jr0, jg1 = j0 + jr1;
    const __nv_bfloat162 z2 = __float2bfloat162_rn(0.0f);

    float bb[3][2];
#pragma unroll
    for (int t = 0; t < 3; t++) {
        int k0 = (ntb + t) * 8 + kq * 2;
        bb[t][0] = (k0 < NLAB) ? b2s[k0] : 0.0f;  // b2s valid after first sync; redo below
        bb[t][1] = (k0 < NLAB) ? 0.0f : 0.0f;
    }
    float mx[3][2];
#pragma unroll
    for (int t = 0; t < 3; t++) mx[t][0] = mx[t][1] = 0.0f;

    __syncthreads();
    // (re)load biases now that b2s is valid
#pragma unroll
    for (int t = 0; t < 3; t++) {
        int k0 = (ntb + t) * 8 + kq * 2;
        bb[t][0] = (k0 < NLAB) ? b2s[k0] : 0.0f;
        bb[t][1] = (k0 + 1 < NLAB) ? b2s[k0 + 1] : 0.0f;
    }

    for (int t7 = 0; t7 < NIT_PER; t7++) {
        const int i0 = (itc * NIT_PER + t7) * 4;

        // build AiC (bf16x2, pair-permuted) + flags
        for (int u = tid; u < 12 * AJW; u += 256) {
            int rc = u / AJW, p = u - rc * AJW;
            int ill = rc / 3, c = rc - ill * 3;
            float2 a = *(const float2*)&g_Ai[(size_t)(b * LSEQ + i0 + ill) * KP + 2 * p];
            float2 cc = *(const float2*)&g_Cc[c * KP + 2 * p];
            AiC[rc * AJW + permp(p)] = pack_bf16(a.x + cc.x, a.y + cc.y);
        }
        for (int t = tid; t < 4 * JT; t += 256) {
            int ill = t >> 4, jl = t & 15;
            int i = i0 + ill, j = j0 + jl;
            int c = 0, valid = 0;
            if (j < LSEQ) {
                valid = (smask[i * LSEQ + j] >= 1) ? 1 : 0;
                if (s <= i && i <= j && j <= e) c = (i == s && j == e) ? 2 : 1;
            }
            cf[t] = (unsigned char)(c | (valid << 2));
        }
        __syncthreads();

        const int f0 = cf[il * JT + jr0], f1 = cf[il * JT + jr1];
        const uint32_t* aj0p = AjS + jr0 * AJW + 2 * kq;
        const uint32_t* aj1p = AjS + jr1 * AJW + 2 * kq;
        const uint32_t* ac0p = AiC + (il * 3 + (f0 & 3)) * AJW + 2 * kq;
        const uint32_t* ac1p = AiC + (il * 3 + (f1 & 3)) * AJW + 2 * kq;
        const uint32_t* wpp = W2s + (ntb * 8 + r) * AJW + 2 * kq;

        float acc[3][4];
#pragma unroll
        for (int t = 0; t < 3; t++)
#pragma unroll
            for (int q = 0; q < 4; q++) acc[t][q] = 0.0f;

#pragma unroll 2
        for (int ks = 0; ks < NCHUNK; ks++) {
            const int off = ks * 8;
            uint2 vaj0 = *(const uint2*)(aj0p + off);
            uint2 vac0 = *(const uint2*)(ac0p + off);
            uint2 vaj1 = *(const uint2*)(aj1p + off);
            uint2 vac1 = *(const uint2*)(ac1p + off);
            unsigned a0 = b2u(__hmax2(__hadd2(u2b(vaj0.x), u2b(vac0.x)), z2));
            unsigned a2 = b2u(__hmax2(__hadd2(u2b(vaj0.y), u2b(vac0.y)), z2));
            unsigned a1 = b2u(__hmax2(__hadd2(u2b(vaj1.x), u2b(vac1.x)), z2));
            unsigned a3 = b2u(__hmax2(__hadd2(u2b(vaj1.y), u2b(vac1.y)), z2));
#pragma unroll
            for (int t = 0; t < 3; t++) {
                if (t < ntn) {
                    uint2 bv = *(const uint2*)(wpp + t * 8 * AJW + off);
                    mma_bf16(acc[t], a0, a1, a2, a3, bv.x, bv.y);
                }
            }
        }

        // epilogue: +b2, mask, store; track per-k max
        const int i = i0 + il;
        const int v0 = (f0 >> 2) & 1, v1 = (f1 >> 2) & 1;
#pragma unroll
        for (int t = 0; t < 3; t++) {
            if (t < ntn) {
                int k0 = (ntb + t) * 8 + kq * 2;
                if (k0 < NLAB) {
                    if (jg0 < LSEQ) {
                        float s0 = v0 ? (acc[t][0] + bb[t][0]) : 0.0f;
                        float s1 = v0 ? (acc[t][1] + bb[t][1]) : 0.0f;
                        size_t p0 = (size_t)(b * NLAB + k0) * LL + (size_t)i * LSEQ + jg0;
                        out[p0] = s0;
                        out[p0 + LL] = s1;
                        mx[t][0] = fmaxf(mx[t][0], s0);
                        mx[t][1] = fmaxf(mx[t][1], s1);
                    }
                    if (jg1 < LSEQ) {
                        float s0 = v1 ? (acc[t][2] + bb[t][0]) : 0.0f;
                        float s1 = v1 ? (acc[t][3] + bb[t][1]) : 0.0f;
                        size_t p1 = (size_t)(b * NLAB + k0) * LL + (size_t)i * LSEQ + jg1;
                        out[p1] = s0;
                        out[p1 + LL] = s1;
                        mx[t][0] = fmaxf(mx[t][0], s0);
                        mx[t][1] = fmaxf(mx[t][1], s1);
                    }
                }
            }
        }
        __syncthreads();  // epilogue loads done before next-iter AiC/cf overwrite
    }

    // fold max over r-lanes (lane = r*4+kq), then atomicMax per label
#pragma unroll
    for (int t = 0; t < 3; t++) {
        if (t < ntn) {
#pragma unroll
            for (int q = 0; q < 2; q++) {
                float m = mx[t][q];
                m = fmaxf(m, __shfl_xor_sync(0xFFFFFFFFu, m, 4));
                m = fmaxf(m, __shfl_xor_sync(0xFFFFFFFFu, m, 8));
                m = fmaxf(m, __shfl_xor_sync(0xFFFFFFFFu, m, 16));
                int k0 = (ntb + t) * 8 + kq * 2 + q;
                if (r == 0 && k0 < NLAB)
                    atomicMax(&g_maxbits[b * NLAB + k0], __float_as_uint(m));
            }
        }
    }
}

// ---------------------------------------------------------------------------
// Partial sum of exp(x - M); 4 independent accumulator chains + 2-way load ILP.
__global__ __launch_bounds__(256) void k_sumexp(const float* __restrict__ out) {
    const int bk = blockIdx.y;
    const float4* p = (const float4*)(out + (size_t)bk * LL);
    const float M = __uint_as_float(g_maxbits[bk]);
    const float L2E = 1.4426950408889634f;
    const float nML2E = -M * L2E;
    const int STR = NPART * 256;
    float s0 = 0.f, s1 = 0.f, s2 = 0.f, s3 = 0.f;
    for (int t = blockIdx.x * 256 + threadIdx.x; t < LL4; t += 2 * STR) {
        float4 v = p[t];
        float4 u = make_float4(0.f, 0.f, 0.f, 0.f);
        int t2 = t + STR;
        bool hi = (t2 < LL4);
        if (hi) u = p[t2];
        s0 += exp2f(fmaf(v.x, L2E, nML2E));
        s1 += exp2f(fmaf(v.y, L2E, nML2E));
        s2 += exp2f(fmaf(v.z, L2E, nML2E));
        s3 += exp2f(fmaf(v.w, L2E, nML2E));
        if (hi) {
            s0 += exp2f(fmaf(u.x, L2E, nML2E));
            s1 += exp2f(fmaf(u.y, L2E, nML2E));
            s2 += exp2f(fmaf(u.z, L2E, nML2E));
            s3 += exp2f(fmaf(u.w, L2E, nML2E));
        }
    }
    float s = (s0 + s1) + (s2 + s3);
#pragma unroll
    for (int o = 16; o > 0; o >>= 1) s += __shfl_xor_sync(0xFFFFFFFFu, s, o);
    __shared__ float sm[8];
    if ((threadIdx.x & 31) == 0) sm[threadIdx.x >> 5] = s;
    __syncthreads();
    if (threadIdx.x == 0) {
        float ss = 0.f;
#pragma unroll
        for (int q = 0; q < 8; q++) ss += sm[q];
        g_psum[bk * NPART + blockIdx.x] = ss;  // fixed slot -> deterministic
    }
}

// Combine partials (fixed order) + subtract lse.
__global__ __launch_bounds__(256) void k_sub(float* __restrict__ out) {
    const int bk = blockIdx.y;
    __shared__ float lse_s;
    if (threadIdx.x == 0) {
        float M = __uint_as_float(g_maxbits[bk]);
        float s = 0.f;
#pragma unroll
        for (int q = 0; q < NPART; q++) s += g_psum[bk * NPART + q];
        lse_s = M + logf(s);
    }
    __syncthreads();
    const float lse = lse_s;
    int t = blockIdx.x * 256 + threadIdx.x;
    if (t < LL4) {
        float4* p = (float4*)(out + (size_t)bk * LL);
        float4 v = p[t];
        v.x -= lse;
        v.y -= lse;
        v.z -= lse;
        v.w -= lse;
        p[t] = v;
    }
}

// ---------------------------------------------------------------------------
extern "C" void kernel_launch(void* const* d_in, const int* in_sizes, int n_in,
                              void* d_out, int out_size) {
    const float* hidden = (const float*)d_in[0];
    const int* spans = (const int*)d_in[1];
    const int* smask = (const int*)d_in[2];
    const float* W1 = (const float*)d_in[3];
    const float* b1 = (const float*)d_in[4];
    const float* W2 = (const float*)d_in[5];
    const float* b2 = (const float*)d_in[6];
    float* out = (float*)d_out;

    cudaFuncSetAttribute(k_main, cudaFuncAttributeMaxDynamicSharedMemorySize, SMEM_MAIN);

    k_prep<<<256, 256>>>(W1, b1, W2);
    k_ph1<<<dim3(25, 8), 128>>>(hidden);
    k_main<<<dim3(JT, 9, 2), 256, SMEM_MAIN>>>(spans, smask, b2, out);
    k_sumexp<<<dim3(NPART, BATCH * NLAB), 256>>>(out);
    k_sub<<<dim3((LL4 + 255) / 256, BATCH * NLAB), 256>>>(out);
}

// round 15
// speedup vs baseline: 1.5746x; 1.1128x over previous
#include <cuda_runtime.h>
#include <cuda_bf16.h>
#include <cstdint>

#define LSEQ 252
#define HID 768
#define MLP 770
#define NLAB 36
#define BATCH 2
#define KP 784            // MLP padded to 49*16
#define KP2 392           // KP/2 (bf16x2 pairs)
#define NPH1 1540         // 2*MLP
#define MROWS 504         // BATCH*LSEQ
#define LL (LSEQ*LSEQ)    // 63504
#define LL4 (LL/4)        // 15876
#define W1STRIDE 1537     // 2*HID+1
#define NPART 16          // softmax partial-sum slots per (b,k)
#define NCHUNK 49         // k16 chunks
#define JT 64             // j's per block
#define AJW 392           // words (bf16x2 pairs) per row; 392 mod 32 = 8

// ---- scratch (device globals; no dynamic allocation allowed) ----
__device__ float g_W1r[NPH1 * HID];            // repacked W1 (B operand rows)
__device__ float g_Ai[MROWS * KP];             // Ai fp32, zero-padded cols [770,784)
__device__ uint32_t g_Ajh[MROWS * KP2];        // Aj bf16x2, PAIR-PERMUTED, pads zeroed
__device__ float g_Cc[3 * KP];                 // b1 + c*w1c, c=0..2
__device__ uint32_t g_W2b[40 * KP2];           // W2 40x784 bf16, k16-element-permuted
__device__ unsigned g_maxbits[BATCH * NLAB];   // per-(b,k) max (>=0, float bits)
__device__ float g_psum[BATCH * NLAB * NPART]; // partial exp-sums

// ---------------------------------------------------------------------------
// pair permutation within each 8-pair (16-element) group:
// stored order [p0,p4,p1,p5,p2,p6,p3,p7] -> LDS.64 at 2*kq gives (p_kq, p_{kq+4})
__device__ __forceinline__ int permp(int p) {
    int g = p >> 3, q = p & 7;
    return g * 8 + ((q & 3) << 1) + (q >> 2);
}

__device__ __forceinline__ unsigned pack_bf16(float lo, float hi) {
    unsigned r;
    asm("cvt.rn.bf16x2.f32 %0, %1, %2;" : "=r"(r) : "f"(hi), "f"(lo));
    return r;
}
__device__ __forceinline__ __nv_bfloat162 u2b(uint32_t x) {
    return *(__nv_bfloat162*)&x;
}
__device__ __forceinline__ uint32_t b2u(__nv_bfloat162 x) {
    return *(uint32_t*)&x;
}

// tf32 mma m16n8k8 (phase-1 GEMM)
__device__ __forceinline__ void mma_tf32(float* d, float a0, float a1, float a2, float a3,
                                         float b0, float b1) {
    asm volatile(
        "mma.sync.aligned.m16n8k8.row.col.f32.tf32.tf32.f32 "
        "{%0,%1,%2,%3},{%4,%5,%6,%7},{%8,%9},{%0,%1,%2,%3};\n"
        : "+f"(d[0]), "+f"(d[1]), "+f"(d[2]), "+f"(d[3])
        : "r"(__float_as_uint(a0)), "r"(__float_as_uint(a1)),
          "r"(__float_as_uint(a2)), "r"(__float_as_uint(a3)),
          "r"(__float_as_uint(b0)), "r"(__float_as_uint(b1)));
}
// bf16 mma m16n8k16 (main GEMM)
__device__ __forceinline__ void mma_bf16(float* d, unsigned a0, unsigned a1, unsigned a2,
                                         unsigned a3, unsigned b0, unsigned b1) {
    asm volatile(
        "mma.sync.aligned.m16n8k16.row.col.f32.bf16.bf16.f32 "
        "{%0,%1,%2,%3},{%4,%5,%6,%7},{%8,%9},{%0,%1,%2,%3};\n"
        : "+f"(d[0]), "+f"(d[1]), "+f"(d[2]), "+f"(d[3])
        : "r"(a0), "r"(a1), "r"(a2), "r"(a3), "r"(b0), "r"(b1));
}

// ---------------------------------------------------------------------------
// Prep: repack W1, C vectors, W2 (k16 element perm), pads, reset max.
__global__ void k_prep(const float* __restrict__ W1, const float* __restrict__ b1,
                       const float* __restrict__ W2) {
    int idx = blockIdx.x * blockDim.x + threadIdx.x;
    int stride = gridDim.x * blockDim.x;
    for (int t = idx; t < NPH1 * HID; t += stride) {
        int n = t / HID, k = t - n * HID;
        g_W1r[t] = (n < MLP) ? W1[n * W1STRIDE + k] : W1[(n - MLP) * W1STRIDE + HID + k];
    }
    for (int t = idx; t < 3 * KP; t += stride) {
        int c = t / KP, h = t - c * KP;
        g_Cc[t] = (h < MLP) ? (b1[h] + (float)c * W1[h * W1STRIDE + 2 * HID]) : 0.0f;
    }
    for (int t = idx; t < 40 * KP2; t += stride) {  // build as bf16x2 words
        int n = t / KP2, p = t - n * KP2;
        int ch = p >> 3, pin = p & 7;
        int pos0 = pin * 2, pos1 = pin * 2 + 1;
        int q0 = pos0 >> 2, q1 = pos1 >> 2;
        int k0 = ch * 16 + (((pos0 & 3) < 2) ? (2 * q0 + (pos0 & 1)) : (8 + 2 * q0 + (pos0 & 1)));
        int k1 = ch * 16 + (((pos1 & 3) < 2) ? (2 * q1 + (pos1 & 1)) : (8 + 2 * q1 + (pos1 & 1)));
        float v0 = (n < NLAB && k0 < MLP) ? W2[n * MLP + k0] : 0.0f;
        float v1 = (n < NLAB && k1 < MLP) ? W2[n * MLP + k1] : 0.0f;
        g_W2b[t] = pack_bf16(v0, v1);
    }
    for (int t = idx; t < MROWS * (KP - MLP); t += stride) {
        int m = t / (KP - MLP), c = MLP + (t - m * (KP - MLP));
        g_Ai[m * KP + c] = 0.0f;
    }
    for (int t = idx; t < MROWS * 7; t += stride) {  // Aj pad pairs 385..391 (perm-closed)
        int m = t / 7, p = 385 + (t - m * 7);
        g_Ajh[m * KP2 + p] = 0u;
    }
    for (int t = idx; t < BATCH * NLAB; t += stride) g_maxbits[t] = 0u;
}

// ---------------------------------------------------------------------------
// Phase 1: [504x768] @ [768x1540] tf32 GEMM -> g_Ai (fp32) / g_Ajh (bf16x2, permuted).
__global__ __launch_bounds__(128) void k_ph1(const float* __restrict__ hidden) {
    __shared__ float As[64 * 36];
    __shared__ float Bs[64 * 36];
    const int tid = threadIdx.x, lane = tid & 31, w = tid >> 5;
    const int m0 = blockIdx.y * 64, n0 = blockIdx.x * 64;
    const int wm = w >> 1, wn = w & 1;
    const int r = lane >> 2, kq = lane & 3;

    float acc[2][4][4];
#pragma unroll
    for (int a = 0; a < 2; a++)
#pragma unroll
        for (int b = 0; b < 4; b++)
#pragma unroll
            for (int c = 0; c < 4; c++) acc[a][b][c] = 0.0f;

    for (int kc = 0; kc < 24; kc++) {
        const int k0 = kc * 32;
#pragma unroll
        for (int p = 0; p < 4; p++) {
            int i = tid + p * 128;
            int row = i >> 3, c8 = i & 7;
            int m = m0 + row;
            float4 v = make_float4(0.f, 0.f, 0.f, 0.f);
            if (m < MROWS) {
                int b = m / LSEQ, l = m - b * LSEQ;
                v = *(const float4*)&hidden[((size_t)(b * (LSEQ + 1) + l + 1)) * HID + k0 + c8 * 4];
            }
            *(float4*)&As[row * 36 + c8 * 4] = v;
        }
#pragma unroll
        for (int p = 0; p < 4; p++) {
            int i = tid + p * 128;
            int row = i >> 3, c8 = i & 7;
            int n = n0 + row;
            float4 v = make_float4(0.f, 0.f, 0.f, 0.f);
            if (n < NPH1) v = *(const float4*)&g_W1r[(size_t)n * HID + k0 + c8 * 4];
            *(float4*)&Bs[row * 36 + c8 * 4] = v;
        }
        __syncthreads();
#pragma unroll
        for (int kk = 0; kk < 4; kk++) {
            const int kb = kk * 8 + kq;
            float a[2][4];
#pragma unroll
            for (int mf = 0; mf < 2; mf++) {
                int rb = wm * 32 + mf * 16 + r;
                a[mf][0] = As[rb * 36 + kb];
                a[mf][1] = As[(rb + 8) * 36 + kb];
                a[mf][2] = As[rb * 36 + kb + 4];
                a[mf][3] = As[(rb + 8) * 36 + kb + 4];
            }
#pragma unroll
            for (int nf = 0; nf < 4; nf++) {
                int nr = wn * 32 + nf * 8 + r;
                float b0 = Bs[nr * 36 + kb];
                float b1 = Bs[nr * 36 + kb + 4];
                mma_tf32(acc[0][nf], a[0][0], a[0][1], a[0][2], a[0][3], b0, b1);
                mma_tf32(acc[1][nf], a[1][0], a[1][1], a[1][2], a[1][3], b0, b1);
            }
        }
        __syncthreads();
    }
#pragma unroll
    for (int mf = 0; mf < 2; mf++) {
#pragma unroll
        for (int nf = 0; nf < 4; nf++) {
            int mg = m0 + wm * 32 + mf * 16 + r;
            int ng = n0 + wn * 32 + nf * 8 + kq * 2;
            if (ng < NPH1) {
                if (ng < MLP) {
                    if (mg < MROWS)
                        *(float2*)&g_Ai[(size_t)mg * KP + ng] =
                            make_float2(acc[mf][nf][0], acc[mf][nf][1]);
                    if (mg + 8 < MROWS)
                        *(float2*)&g_Ai[(size_t)(mg + 8) * KP + ng] =
                            make_float2(acc[mf][nf][2], acc[mf][nf][3]);
                } else {
                    int p = permp((ng - MLP) >> 1);
                    if (mg < MROWS)
                        g_Ajh[(size_t)mg * KP2 + p] = pack_bf16(acc[mf][nf][0], acc[mf][nf][1]);
                    if (mg + 8 < MROWS)
                        g_Ajh[(size_t)(mg + 8) * KP2 + p] =
                            pack_bf16(acc[mf][nf][2], acc[mf][nf][3]);
                }
            }
        }
    }
}

// ---------------------------------------------------------------------------
// Main fused kernel: JT=64 j's, 512 threads (16 warps = 4 il x 4 jh), occ 1.
// Every warp computes ALL 5 n-tiles -> A fragments amortized over N=40.
// i-slabs: itc<9 -> 4 slabs, itc>=9 -> 3 slabs (63 = 9*4 + 9*3).
#define SMW_AJ 0                      // [64][392] uint32
#define SMW_AIC (JT * AJW)            // [12][392]
#define SMW_W2 (SMW_AIC + 12 * AJW)   // [40][392]
#define SMW_B2 (SMW_W2 + 40 * AJW)    // 40 floats
#define SMW_CF (SMW_B2 + 40)          // 256 bytes (64 words)
#define SMEM_MAIN ((SMW_CF + 64) * 4)

__global__ __launch_bounds__(512, 1) void k_main(const int* __restrict__ spans,
                                                 const int* __restrict__ smask,
                                                 const float* __restrict__ b2,
                                                 float* __restrict__ out) {
    extern __shared__ uint32_t smw[];
    uint32_t* AjS = smw + SMW_AJ;
    uint32_t* AiC = smw + SMW_AIC;
    uint32_t* W2s = smw + SMW_W2;
    float* b2s = (float*)(smw + SMW_B2);
    unsigned char* cf = (unsigned char*)(smw + SMW_CF);

    const int tid = threadIdx.x;
    const int b = blockIdx.z, itc = blockIdx.y, jt = blockIdx.x;
    const int j0 = jt * JT;
    const int s = spans[b * 2], e = spans[b * 2 + 1];
    const int slab0 = (itc < 9) ? itc * 4 : 36 + (itc - 9) * 3;
    const int nslab = (itc < 9) ? 4 : 3;

    // ---- one-time prologue ----
    for (int u = tid; u < JT * AJW; u += 512) {
        int row = u / AJW, p = u - row * AJW;
        int j = j0 + row;
        AjS[u] = (j < LSEQ) ? g_Ajh[(size_t)(b * LSEQ + j) * KP2 + p] : 0u;
    }
    for (int u = tid; u < 40 * AJW / 4; u += 512)
        ((uint4*)W2s)[u] = ((const uint4*)g_W2b)[u];
    if (tid < 40) b2s[tid] = (tid < NLAB) ? b2[tid] : 0.0f;

    const int lane = tid & 31, w = tid >> 5;
    const int il = w >> 2, jh = w & 3;
    const int r = lane >> 2, kq = lane & 3;
    const int jr0 = jh * 16 + r, jr1 = jr0 + 8;
    const int jg0 = j0 + jr0, jg1 = j0 + jr1;
    const __nv_bfloat162 z2 = __float2bfloat162_rn(0.0f);

    __syncthreads();

    float bb[5][2];
#pragma unroll
    for (int t = 0; t < 5; t++) {
        int k0 = t * 8 + kq * 2;
        bb[t][0] = (k0 < NLAB) ? b2s[k0] : 0.0f;
        bb[t][1] = (k0 + 1 < NLAB) ? b2s[k0 + 1] : 0.0f;
    }
    float mx[5][2];
#pragma unroll
    for (int t = 0; t < 5; t++) mx[t][0] = mx[t][1] = 0.0f;

    for (int t7 = 0; t7 < nslab; t7++) {
        const int i0 = (slab0 + t7) * 4;

        // build AiC (bf16x2, pair-permuted) + flags
        for (int u = tid; u < 12 * AJW; u += 512) {
            int rc = u / AJW, p = u - rc * AJW;
            int ill = rc / 3, c = rc - ill * 3;
            float2 a = *(const float2*)&g_Ai[(size_t)(b * LSEQ + i0 + ill) * KP + 2 * p];
            float2 cc = *(const float2*)&g_Cc[c * KP + 2 * p];
            AiC[rc * AJW + permp(p)] = pack_bf16(a.x + cc.x, a.y + cc.y);
        }
        if (tid < 4 * JT) {
            int ill = tid >> 6, jl = tid & 63;
            int i = i0 + ill, j = j0 + jl;
            int c = 0, valid = 0;
            if (j < LSEQ) {
                valid = (smask[i * LSEQ + j] >= 1) ? 1 : 0;
                if (s <= i && i <= j && j <= e) c = (i == s && j == e) ? 2 : 1;
            }
            cf[tid] = (unsigned char)(c | (valid << 2));
        }
        __syncthreads();

        const int f0 = cf[il * JT + jr0], f1 = cf[il * JT + jr1];
        const uint32_t* aj0p = AjS + jr0 * AJW + 2 * kq;
        const uint32_t* aj1p = AjS + jr1 * AJW + 2 * kq;
        const uint32_t* ac0p = AiC + (il * 3 + (f0 & 3)) * AJW + 2 * kq;
        const uint32_t* ac1p = AiC + (il * 3 + (f1 & 3)) * AJW + 2 * kq;
        const uint32_t* wpp = W2s + r * AJW + 2 * kq;

        float acc[5][4];
#pragma unroll
        for (int t = 0; t < 5; t++)
#pragma unroll
            for (int q = 0; q < 4; q++) acc[t][q] = 0.0f;

#pragma unroll 2
        for (int ks = 0; ks < NCHUNK; ks++) {
            const int off = ks * 8;
            uint2 vaj0 = *(const uint2*)(aj0p + off);
            uint2 vac0 = *(const uint2*)(ac0p + off);
            uint2 vaj1 = *(const uint2*)(aj1p + off);
            uint2 vac1 = *(const uint2*)(ac1p + off);
            unsigned a0 = b2u(__hmax2(__hadd2(u2b(vaj0.x), u2b(vac0.x)), z2));
            unsigned a2 = b2u(__hmax2(__hadd2(u2b(vaj0.y), u2b(vac0.y)), z2));
            unsigned a1 = b2u(__hmax2(__hadd2(u2b(vaj1.x), u2b(vac1.x)), z2));
            unsigned a3 = b2u(__hmax2(__hadd2(u2b(vaj1.y), u2b(vac1.y)), z2));
#pragma unroll
            for (int t = 0; t < 5; t++) {
                uint2 bv = *(const uint2*)(wpp + t * 8 * AJW + off);
                mma_bf16(acc[t], a0, a1, a2, a3, bv.x, bv.y);
            }
        }

        // epilogue: +b2, mask, store; track per-k max
        const int i = i0 + il;
        const int v0 = (f0 >> 2) & 1, v1 = (f1 >> 2) & 1;
#pragma unroll
        for (int t = 0; t < 5; t++) {
            int k0 = t * 8 + kq * 2;
            if (k0 < NLAB) {
                if (jg0 < LSEQ) {
                    float s0 = v0 ? (acc[t][0] + bb[t][0]) : 0.0f;
                    float s1 = v0 ? (acc[t][1] + bb[t][1]) : 0.0f;
                    size_t p0 = (size_t)(b * NLAB + k0) * LL + (size_t)i * LSEQ + jg0;
                    out[p0] = s0;
                    out[p0 + LL] = s1;
                    mx[t][0] = fmaxf(mx[t][0], s0);
                    mx[t][1] = fmaxf(mx[t][1], s1);
                }
                if (jg1 < LSEQ) {
                    float s0 = v1 ? (acc[t][2] + bb[t][0]) : 0.0f;
                    float s1 = v1 ? (acc[t][3] + bb[t][1]) : 0.0f;
                    size_t p1 = (size_t)(b * NLAB + k0) * LL + (size_t)i * LSEQ + jg1;
                    out[p1] = s0;
                    out[p1 + LL] = s1;
                    mx[t][0] = fmaxf(mx[t][0], s0);
                    mx[t][1] = fmaxf(mx[t][1], s1);
                }
            }
        }
        __syncthreads();  // epilogue done before next-iter AiC/cf overwrite
    }

    // fold max over r-lanes (lane = r*4+kq), then atomicMax per label
#pragma unroll
    for (int t = 0; t < 5; t++) {
#pragma unroll
        for (int q = 0; q < 2; q++) {
            float m = mx[t][q];
            m = fmaxf(m, __shfl_xor_sync(0xFFFFFFFFu, m, 4));
            m = fmaxf(m, __shfl_xor_sync(0xFFFFFFFFu, m, 8));
            m = fmaxf(m, __shfl_xor_sync(0xFFFFFFFFu, m, 16));
            int k0 = t * 8 + kq * 2 + q;
            if (r == 0 && k0 < NLAB)
                atomicMax(&g_maxbits[b * NLAB + k0], __float_as_uint(m));
        }
    }
}

// ---------------------------------------------------------------------------
// Partial sum of exp(x - M); 4 independent accumulator chains + 2-way load ILP.
__global__ __launch_bounds__(256) void k_sumexp(const float* __restrict__ out) {
    const int bk = blockIdx.y;
    const float4* p = (const float4*)(out + (size_t)bk * LL);
    const float M = __uint_as_float(g_maxbits[bk]);
    const float L2E = 1.4426950408889634f;
    const float nML2E = -M * L2E;
    const int STR = NPART * 256;
    float s0 = 0.f, s1 = 0.f, s2 = 0.f, s3 = 0.f;
    for (int t = blockIdx.x * 256 + threadIdx.x; t < LL4; t += 2 * STR) {
        float4 v = p[t];
        float4 u = make_float4(0.f, 0.f, 0.f, 0.f);
        int t2 = t + STR;
        bool hi = (t2 < LL4);
        if (hi) u = p[t2];
        s0 += exp2f(fmaf(v.x, L2E, nML2E));
        s1 += exp2f(fmaf(v.y, L2E, nML2E));
        s2 += exp2f(fmaf(v.z, L2E, nML2E));
        s3 += exp2f(fmaf(v.w, L2E, nML2E));
        if (hi) {
            s0 += exp2f(fmaf(u.x, L2E, nML2E));
            s1 += exp2f(fmaf(u.y, L2E, nML2E));
            s2 += exp2f(fmaf(u.z, L2E, nML2E));
            s3 += exp2f(fmaf(u.w, L2E, nML2E));
        }
    }
    float s = (s0 + s1) + (s2 + s3);
#pragma unroll
    for (int o = 16; o > 0; o >>= 1) s += __shfl_xor_sync(0xFFFFFFFFu, s, o);
    __shared__ float sm[8];
    if ((threadIdx.x & 31) == 0) sm[threadIdx.x >> 5] = s;
    __syncthreads();
    if (threadIdx.x == 0) {
        float ss = 0.f;
#pragma unroll
        for (int q = 0; q < 8; q++) ss += sm[q];
        g_psum[bk * NPART + blockIdx.x] = ss;  // fixed slot -> deterministic
    }
}

// Combine partials (fixed order) + subtract lse.
__global__ __launch_bounds__(256) void k_sub(float* __restrict__ out) {
    const int bk = blockIdx.y;
    __shared__ float lse_s;
    if (threadIdx.x == 0) {
        float M = __uint_as_float(g_maxbits[bk]);
        float s = 0.f;
#pragma unroll
        for (int q = 0; q < NPART; q++) s += g_psum[bk * NPART + q];
        lse_s = M + logf(s);
    }
    __syncthreads();
    const float lse = lse_s;
    int t = blockIdx.x * 256 + threadIdx.x;
    if (t < LL4) {
        float4* p = (float4*)(out + (size_t)bk * LL);
        float4 v = p[t];
        v.x -= lse;
        v.y -= lse;
        v.z -= lse;
        v.w -= lse;
        p[t] = v;
    }
}

// ---------------------------------------------------------------------------
extern "C" void kernel_launch(void* const* d_in, const int* in_sizes, int n_in,
                              void* d_out, int out_size) {
    const float* hidden = (const float*)d_in[0];
    const int* spans = (const int*)d_in[1];
    const int* smask = (const int*)d_in[2];
    const float* W1 = (const float*)d_in[3];
    const float* b1 = (const float*)d_in[4];
    const float* W2 = (const float*)d_in[5];
    const float* b2 = (const float*)d_in[6];
    float* out = (float*)d_out;

    cudaFuncSetAttribute(k_main, cudaFuncAttributeMaxDynamicSharedMemorySize, SMEM_MAIN);

    k_prep<<<256, 256>>>(W1, b1, W2);
    k_ph1<<<dim3(25, 8), 128>>>(hidden);
    k_main<<<dim3(4, 18, 2), 512, SMEM_MAIN>>>(spans, smask, b2, out);
    k_sumexp<<<dim3(NPART, BATCH * NLAB), 256>>>(out);
    k_sub<<<dim3((LL4 + 255) / 256, BATCH * NLAB), 256>>>(out);
}